// round 2
// baseline (speedup 1.0000x reference)
#include <cuda_runtime.h>
#include <math.h>

#define N_NODES 50000
#define IN_DIM  27
#define F1      256
#define H1      4
#define F2      128
#define H2      2

// ---------------- scratch (no allocations allowed) ----------------
__device__ float g_h1  [N_NODES * F1];   // layer1 linear output h = x@W1
__device__ float g_agg1[N_NODES * F1];   // layer1 aggregation / elu output
__device__ float g_h2  [N_NODES * F2];   // layer2 linear output
__device__ float g_agg2[N_NODES * F2];   // layer2 aggregation / elu output
__device__ float g_ss  [N_NODES * H1];   // per-node src half-scores (max heads)
__device__ float g_sd  [N_NODES * H1];   // per-node dst half-scores
__device__ float g_m   [N_NODES * H1];   // segment max
__device__ float g_z   [N_NODES * H1];   // segment sum of exp

__device__ __forceinline__ void atomicMaxFloat(float* addr, float val) {
    if (val >= 0.f)
        atomicMax((int*)addr, __float_as_int(val));
    else
        atomicMin((unsigned int*)addr, (unsigned int)__float_as_int(val));
}

// ---------------- GEMM1: x[N,27] @ W1[27,256] -> h1[N,256] ----------------
__global__ void gemm1_kernel(const float* __restrict__ x,
                             const float* __restrict__ W,
                             float* __restrict__ out) {
    __shared__ float Ws[IN_DIM * F1];   // 27*256 floats = 27KB
    __shared__ float xs[64 * IN_DIM];
    int t = threadIdx.x;                // 256 threads
    for (int i = t; i < IN_DIM * F1; i += 256) Ws[i] = W[i];
    int r0 = blockIdx.x * 64;
    for (int i = t; i < 64 * IN_DIM; i += 256) {
        int r = i / IN_DIM, c = i % IN_DIM;
        int gr = r0 + r;
        xs[i] = (gr < N_NODES) ? x[gr * IN_DIM + c] : 0.f;
    }
    __syncthreads();
    float w[IN_DIM];
#pragma unroll
    for (int k = 0; k < IN_DIM; k++) w[k] = Ws[k * F1 + t];
    for (int r = 0; r < 64; r++) {
        int gr = r0 + r;
        if (gr >= N_NODES) break;
        float acc = 0.f;
#pragma unroll
        for (int k = 0; k < IN_DIM; k++) acc += xs[r * IN_DIM + k] * w[k];
        out[(size_t)gr * F1 + t] = acc;
    }
}

// ---------------- per-node attention half-scores ----------------
// one warp per (node, head); dim = 64
template<int H>
__global__ void scores_kernel(const float* __restrict__ h,
                              const float* __restrict__ asrc,
                              const float* __restrict__ adst,
                              float* __restrict__ ss, float* __restrict__ sd) {
    int gid  = blockIdx.x * blockDim.x + threadIdx.x;
    int warp = gid >> 5, lane = gid & 31;
    if (warp >= N_NODES * H) return;
    int n = warp / H, hh = warp % H;
    const float* hp = h + (size_t)n * (H * 64) + hh * 64;
    const float* as = asrc + hh * 64;
    const float* ad = adst + hh * 64;
    float v0 = hp[lane], v1 = hp[lane + 32];
    float s1 = v0 * as[lane] + v1 * as[lane + 32];
    float s2 = v0 * ad[lane] + v1 * ad[lane + 32];
#pragma unroll
    for (int o = 16; o > 0; o >>= 1) {
        s1 += __shfl_down_sync(0xffffffffu, s1, o);
        s2 += __shfl_down_sync(0xffffffffu, s2, o);
    }
    if (lane == 0) { ss[warp] = s1; sd[warp] = s2; }
}

// ---------------- init m/z/agg ----------------
template<int H, int F>
__global__ void init_kernel(float* __restrict__ m, float* __restrict__ z,
                            float* __restrict__ agg) {
    int i = blockIdx.x * blockDim.x + threadIdx.x;
    if (i < N_NODES * H) { m[i] = -INFINITY; z[i] = 0.f; }
    if (i < N_NODES * F) agg[i] = 0.f;
}

// ---------------- edge pass 1: segment max of leaky-relu logits ----------------
template<int H>
__global__ void edge_max_kernel(const int* __restrict__ ei, int E, int ET,
                                const float* __restrict__ ss,
                                const float* __restrict__ sd,
                                float* __restrict__ m) {
    int e = blockIdx.x * blockDim.x + threadIdx.x;
    if (e >= ET) return;
    int src, dst;
    if (e < E) { src = ei[e]; dst = ei[E + e]; }
    else       { src = dst = e - E; }
#pragma unroll
    for (int h = 0; h < H; h++) {
        float l = ss[src * H + h] + sd[dst * H + h];
        l = (l > 0.f) ? l : 0.2f * l;
        atomicMaxFloat(&m[dst * H + h], l);
    }
}

// ---------------- edge pass 2: z += e ; agg += e * h[src] ----------------
// one warp per edge
template<int H, int F>
__global__ void edge_agg_kernel(const int* __restrict__ ei, int E, int ET,
                                const float* __restrict__ ss,
                                const float* __restrict__ sd,
                                const float* __restrict__ m,
                                float* __restrict__ z,
                                const float* __restrict__ h,
                                float* __restrict__ agg) {
    int gid = blockIdx.x * blockDim.x + threadIdx.x;
    int e = gid >> 5, lane = gid & 31;
    if (e >= ET) return;
    int src, dst;
    if (e < E) { src = ei[e]; dst = ei[E + e]; }
    else       { src = dst = e - E; }
    float ev = 0.f;
    if (lane < H) {
        float l = ss[src * H + lane] + sd[dst * H + lane];
        l = (l > 0.f) ? l : 0.2f * l;
        ev = __expf(l - m[dst * H + lane]);
        atomicAdd(&z[dst * H + lane], ev);
    }
    const float* hs = h + (size_t)src * F;
    float* ag = agg + (size_t)dst * F;
#pragma unroll
    for (int i = 0; i < F / 32; i++) {
        int c = lane + i * 32;
        float evc = __shfl_sync(0xffffffffu, ev, c >> 6);  // head = c/64
        atomicAdd(&ag[c], evc * hs[c]);
    }
}

// ---------------- finalize: normalize by z, add bias, elu (in place) ----------------
template<int H, int F>
__global__ void finalize_kernel(float* __restrict__ agg,
                                const float* __restrict__ z,
                                const float* __restrict__ b) {
    int i = blockIdx.x * blockDim.x + threadIdx.x;
    if (i >= N_NODES * F) return;
    int c = i % F, n = i / F;
    int hh = c >> 6;
    float v = agg[i] / (z[n * H + hh] + 1e-16f) + b[c];
    agg[i] = (v > 0.f) ? v : expm1f(v);
}

// ---------------- GEMM2: A[M,256] @ B[256,128] -> C[M,128] ----------------
__global__ void gemm2_kernel(const float* __restrict__ A,
                             const float* __restrict__ B,
                             float* __restrict__ C) {
    __shared__ float As[64][33];
    __shared__ float Bs[32][128];
    int t = threadIdx.x;                 // 256 threads
    int tx = t & 15, ty = t >> 4;        // 16 x 16
    int row0 = blockIdx.x * 64;
    float acc[4][8];
#pragma unroll
    for (int i = 0; i < 4; i++)
#pragma unroll
        for (int j = 0; j < 8; j++) acc[i][j] = 0.f;

    for (int kt = 0; kt < 256; kt += 32) {
#pragma unroll
        for (int s = 0; s < 2; s++) {
            int i = t + s * 256;          // float4 index into 64x32 tile
            int r = i >> 3, k4 = i & 7;
            int gr = row0 + r;
            float4 v = make_float4(0.f, 0.f, 0.f, 0.f);
            if (gr < N_NODES) v = *(const float4*)&A[(size_t)gr * 256 + kt + k4 * 4];
            As[r][k4 * 4 + 0] = v.x; As[r][k4 * 4 + 1] = v.y;
            As[r][k4 * 4 + 2] = v.z; As[r][k4 * 4 + 3] = v.w;
        }
#pragma unroll
        for (int s = 0; s < 4; s++) {
            int i = t + s * 256;          // float4 index into 32x128 tile
            int k = i >> 5, c4 = i & 31;
            *(float4*)&Bs[k][c4 * 4] = *(const float4*)&B[(size_t)(kt + k) * 128 + c4 * 4];
        }
        __syncthreads();
#pragma unroll
        for (int k = 0; k < 32; k++) {
            float a0 = As[ty * 4 + 0][k];
            float a1 = As[ty * 4 + 1][k];
            float a2 = As[ty * 4 + 2][k];
            float a3 = As[ty * 4 + 3][k];
            float4 b0 = *(float4*)&Bs[k][tx * 8];
            float4 b1 = *(float4*)&Bs[k][tx * 8 + 4];
            float bb[8] = {b0.x, b0.y, b0.z, b0.w, b1.x, b1.y, b1.z, b1.w};
#pragma unroll
            for (int j = 0; j < 8; j++) {
                acc[0][j] += a0 * bb[j];
                acc[1][j] += a1 * bb[j];
                acc[2][j] += a2 * bb[j];
                acc[3][j] += a3 * bb[j];
            }
        }
        __syncthreads();
    }
#pragma unroll
    for (int i = 0; i < 4; i++) {
        int gr = row0 + ty * 4 + i;
        if (gr >= N_NODES) continue;
        float4 o0 = make_float4(acc[i][0], acc[i][1], acc[i][2], acc[i][3]);
        float4 o1 = make_float4(acc[i][4], acc[i][5], acc[i][6], acc[i][7]);
        *(float4*)&C[(size_t)gr * 128 + tx * 8]     = o0;
        *(float4*)&C[(size_t)gr * 128 + tx * 8 + 4] = o1;
    }
}

// ---------------- final: sigmoid(h[N,128] @ Wfc[128,1] + bfc) ----------------
__global__ void out_kernel(const float* __restrict__ h,
                           const float* __restrict__ Wfc,
                           const float* __restrict__ bfc,
                           float* __restrict__ out) {
    int gid = blockIdx.x * blockDim.x + threadIdx.x;
    int n = gid >> 5, lane = gid & 31;
    if (n >= N_NODES) return;
    const float* hp = h + (size_t)n * 128;
    float s = hp[lane]      * Wfc[lane]
            + hp[lane + 32] * Wfc[lane + 32]
            + hp[lane + 64] * Wfc[lane + 64]
            + hp[lane + 96] * Wfc[lane + 96];
#pragma unroll
    for (int o = 16; o > 0; o >>= 1) s += __shfl_down_sync(0xffffffffu, s, o);
    if (lane == 0) {
        float v = s + bfc[0];
        out[n] = 1.f / (1.f + __expf(-v));
    }
}

// ---------------- launch ----------------
extern "C" void kernel_launch(void* const* d_in, const int* in_sizes, int n_in,
                              void* d_out, int out_size) {
    const float* x      = (const float*)d_in[0];
    const int*   ei     = (const int*)  d_in[1];   // jax default x64-disabled -> int32
    const float* W1     = (const float*)d_in[2];
    const float* a_src1 = (const float*)d_in[3];
    const float* a_dst1 = (const float*)d_in[4];
    const float* b1     = (const float*)d_in[5];
    const float* W2     = (const float*)d_in[6];
    const float* a_src2 = (const float*)d_in[7];
    const float* a_dst2 = (const float*)d_in[8];
    const float* b2     = (const float*)d_in[9];
    const float* Wfc    = (const float*)d_in[10];
    const float* bfc    = (const float*)d_in[11];
    float* out = (float*)d_out;

    int E  = in_sizes[1] / 2;
    int ET = E + N_NODES;

    float *h1, *agg1, *h2, *agg2, *ss, *sd, *m, *z;
    cudaGetSymbolAddress((void**)&h1,   g_h1);
    cudaGetSymbolAddress((void**)&agg1, g_agg1);
    cudaGetSymbolAddress((void**)&h2,   g_h2);
    cudaGetSymbolAddress((void**)&agg2, g_agg2);
    cudaGetSymbolAddress((void**)&ss,   g_ss);
    cudaGetSymbolAddress((void**)&sd,   g_sd);
    cudaGetSymbolAddress((void**)&m,    g_m);
    cudaGetSymbolAddress((void**)&z,    g_z);

    const int TB = 256;
    int blocks_nodes64 = (N_NODES + 63) / 64;

    // ===== layer 1 (H=4, F=256) =====
    gemm1_kernel<<<blocks_nodes64, TB>>>(x, W1, h1);
    scores_kernel<H1><<<(N_NODES * H1 * 32 + TB - 1) / TB, TB>>>(h1, a_src1, a_dst1, ss, sd);
    init_kernel<H1, F1><<<(N_NODES * F1 + TB - 1) / TB, TB>>>(m, z, agg1);
    edge_max_kernel<H1><<<(ET + TB - 1) / TB, TB>>>(ei, E, ET, ss, sd, m);
    edge_agg_kernel<H1, F1><<<(ET * 32 + TB - 1) / TB, TB>>>(ei, E, ET, ss, sd, m, z, h1, agg1);
    finalize_kernel<H1, F1><<<(N_NODES * F1 + TB - 1) / TB, TB>>>(agg1, z, b1);

    // ===== layer 2 (H=2, F=128) =====
    gemm2_kernel<<<blocks_nodes64, TB>>>(agg1, W2, h2);
    scores_kernel<H2><<<(N_NODES * H2 * 32 + TB - 1) / TB, TB>>>(h2, a_src2, a_dst2, ss, sd);
    init_kernel<H2, F2><<<(N_NODES * F2 + TB - 1) / TB, TB>>>(m, z, agg2);
    edge_max_kernel<H2><<<(ET + TB - 1) / TB, TB>>>(ei, E, ET, ss, sd, m);
    edge_agg_kernel<H2, F2><<<(ET * 32 + TB - 1) / TB, TB>>>(ei, E, ET, ss, sd, m, z, h2, agg2);
    finalize_kernel<H2, F2><<<(N_NODES * F2 + TB - 1) / TB, TB>>>(agg2, z, b2);

    // ===== final linear + sigmoid =====
    out_kernel<<<(N_NODES * 32 + TB - 1) / TB, TB>>>(agg2, Wfc, bfc, out);
}

// round 3
// speedup vs baseline: 1.1900x; 1.1900x over previous
#include <cuda_runtime.h>
#include <math.h>

#define N_NODES 50000
#define IN_DIM  27
#define F1      256
#define H1      4
#define F2      128
#define H2      2

// ---------------- scratch (no allocations allowed) ----------------
__device__ float g_h1  [N_NODES * F1];
__device__ float g_agg1[N_NODES * F1];
__device__ float g_h2  [N_NODES * F2];
__device__ float g_agg2[N_NODES * F2];
__device__ float g_ss  [N_NODES * H1];
__device__ float g_sd  [N_NODES * H1];
__device__ float g_m   [N_NODES * H1];
__device__ float g_z   [N_NODES * H1];

__device__ __forceinline__ void atomicMaxFloat(float* addr, float val) {
    if (val >= 0.f)
        atomicMax((int*)addr, __float_as_int(val));
    else
        atomicMin((unsigned int*)addr, (unsigned int)__float_as_int(val));
}

__device__ __forceinline__ void red_add_f4(float* p, float4 v) {
    asm volatile("red.global.add.v4.f32 [%0], {%1, %2, %3, %4};"
                 :: "l"(p), "f"(v.x), "f"(v.y), "f"(v.z), "f"(v.w) : "memory");
}

// ---------------- GEMM1: x[N,27] @ W1[27,256] -> h1[N,256] ----------------
__global__ void gemm1_kernel(const float* __restrict__ x,
                             const float* __restrict__ W,
                             float* __restrict__ out) {
    __shared__ float Ws[IN_DIM * F1];
    __shared__ float xs[64 * IN_DIM];
    int t = threadIdx.x;                // 256 threads
    for (int i = t; i < IN_DIM * F1; i += 256) Ws[i] = W[i];
    int r0 = blockIdx.x * 64;
    for (int i = t; i < 64 * IN_DIM; i += 256) {
        int r = i / IN_DIM, c = i % IN_DIM;
        int gr = r0 + r;
        xs[i] = (gr < N_NODES) ? x[gr * IN_DIM + c] : 0.f;
    }
    __syncthreads();
    float w[IN_DIM];
#pragma unroll
    for (int k = 0; k < IN_DIM; k++) w[k] = Ws[k * F1 + t];
    for (int r = 0; r < 64; r++) {
        int gr = r0 + r;
        if (gr >= N_NODES) break;
        float acc = 0.f;
#pragma unroll
        for (int k = 0; k < IN_DIM; k++) acc += xs[r * IN_DIM + k] * w[k];
        out[(size_t)gr * F1 + t] = acc;
    }
}

// ---------------- per-node attention half-scores ----------------
template<int H>
__global__ void scores_kernel(const float* __restrict__ h,
                              const float* __restrict__ asrc,
                              const float* __restrict__ adst,
                              float* __restrict__ ss, float* __restrict__ sd) {
    int gid  = blockIdx.x * blockDim.x + threadIdx.x;
    int warp = gid >> 5, lane = gid & 31;
    if (warp >= N_NODES * H) return;
    int n = warp / H, hh = warp % H;
    const float* hp = h + (size_t)n * (H * 64) + hh * 64;
    const float* as = asrc + hh * 64;
    const float* ad = adst + hh * 64;
    float v0 = hp[lane], v1 = hp[lane + 32];
    float s1 = v0 * as[lane] + v1 * as[lane + 32];
    float s2 = v0 * ad[lane] + v1 * ad[lane + 32];
#pragma unroll
    for (int o = 16; o > 0; o >>= 1) {
        s1 += __shfl_down_sync(0xffffffffu, s1, o);
        s2 += __shfl_down_sync(0xffffffffu, s2, o);
    }
    if (lane == 0) { ss[warp] = s1; sd[warp] = s2; }
}

// ---------------- init m=-inf, z=0 ----------------
template<int H>
__global__ void init_mz_kernel(float* __restrict__ m, float* __restrict__ z) {
    int i = blockIdx.x * blockDim.x + threadIdx.x;
    if (i < N_NODES * H) { m[i] = -INFINITY; z[i] = 0.f; }
}

// ---------------- edge pass 1: segment max of leaky-relu logits ----------------
template<int H>
__global__ void edge_max_kernel(const int* __restrict__ ei, int E, int ET,
                                const float* __restrict__ ss,
                                const float* __restrict__ sd,
                                float* __restrict__ m) {
    int e = blockIdx.x * blockDim.x + threadIdx.x;
    if (e >= ET) return;
    int src, dst;
    if (e < E) { src = ei[e]; dst = ei[E + e]; }
    else       { src = dst = e - E; }
    float sv[H], dv[H];
    if (H == 4) {
        float4 a = *(const float4*)&ss[src * 4];
        float4 b = *(const float4*)&sd[dst * 4];
        sv[0]=a.x; sv[1]=a.y; sv[2]=a.z; sv[3]=a.w;
        dv[0]=b.x; dv[1]=b.y; dv[2]=b.z; dv[3]=b.w;
    } else {
        float2 a = *(const float2*)&ss[src * 2];
        float2 b = *(const float2*)&sd[dst * 2];
        sv[0]=a.x; sv[1]=a.y; dv[0]=b.x; dv[1]=b.y;
    }
#pragma unroll
    for (int h = 0; h < H; h++) {
        float l = sv[h] + dv[h];
        l = (l > 0.f) ? l : 0.2f * l;
        atomicMaxFloat(&m[dst * H + h], l);
    }
}

// ---------------- edge pass 2: z += e ; agg += e * h[src] (vector RED) ----------------
// one warp per edge; each lane owns float4 chunks
template<int H, int F>
__global__ void edge_agg_kernel(const int* __restrict__ ei, int E, int ET,
                                const float* __restrict__ ss,
                                const float* __restrict__ sd,
                                const float* __restrict__ m,
                                float* __restrict__ z,
                                const float* __restrict__ h,
                                float* __restrict__ agg) {
    int gid = blockIdx.x * blockDim.x + threadIdx.x;
    int e = gid >> 5, lane = gid & 31;
    if (e >= ET) return;
    int src, dst;
    if (e < E) { src = ei[e]; dst = ei[E + e]; }
    else       { src = dst = e - E; }
    float ev = 0.f;
    if (lane < H) {
        float l = ss[src * H + lane] + sd[dst * H + lane];
        l = (l > 0.f) ? l : 0.2f * l;
        ev = __expf(l - m[dst * H + lane]);
        atomicAdd(&z[dst * H + lane], ev);
    }
    const float4* hs = (const float4*)(h + (size_t)src * F);
    float* ag = agg + (size_t)dst * F;
#pragma unroll
    for (int i = 0; i < F / 128; i++) {
        int f = lane + i * 32;                          // float4 index; col = 4f
        float evc = __shfl_sync(0xffffffffu, ev, f >> 4); // head = 4f/64 = f>>4
        float4 v = hs[f];
        v.x *= evc; v.y *= evc; v.z *= evc; v.w *= evc;
        red_add_f4(ag + f * 4, v);
    }
}

// ---------------- finalize: normalize by z, add bias, elu (in place) ----------------
template<int H, int F>
__global__ void finalize_kernel(float* __restrict__ agg,
                                const float* __restrict__ z,
                                const float* __restrict__ b) {
    int i = blockIdx.x * blockDim.x + threadIdx.x;
    if (i >= N_NODES * F) return;
    int c = i % F, n = i / F;
    int hh = c >> 6;
    float v = agg[i] / (z[n * H + hh] + 1e-16f) + b[c];
    agg[i] = (v > 0.f) ? v : expm1f(v);
}

// ---------------- GEMM2: A[M,256] @ B[256,128] -> C[M,128] ----------------
// 128x128 block tile, 256 threads, 8x8 per thread
__global__ void gemm2_kernel(const float* __restrict__ A,
                             const float* __restrict__ B,
                             float* __restrict__ C) {
    __shared__ float As[16][132];   // transposed: As[k][m]
    __shared__ float Bs[16][128];
    int t = threadIdx.x;            // 256 threads
    int tx = t & 15, ty = t >> 4;
    int row0 = blockIdx.x * 128;
    float acc[8][8];
#pragma unroll
    for (int i = 0; i < 8; i++)
#pragma unroll
        for (int j = 0; j < 8; j++) acc[i][j] = 0.f;

    for (int kt = 0; kt < 256; kt += 16) {
#pragma unroll
        for (int s = 0; s < 2; s++) {
            int i = t + s * 256;     // [0,512): 128 rows x 4 k-quads
            int r = i >> 2, kq = i & 3;
            int gr = row0 + r;
            float4 v = make_float4(0.f, 0.f, 0.f, 0.f);
            if (gr < N_NODES) v = *(const float4*)&A[(size_t)gr * 256 + kt + kq * 4];
            As[kq * 4 + 0][r] = v.x;
            As[kq * 4 + 1][r] = v.y;
            As[kq * 4 + 2][r] = v.z;
            As[kq * 4 + 3][r] = v.w;
        }
#pragma unroll
        for (int s = 0; s < 2; s++) {
            int i = t + s * 256;     // [0,512): 16 k x 32 col-quads
            int k = i >> 5, c = i & 31;
            *(float4*)&Bs[k][c * 4] = *(const float4*)&B[(size_t)(kt + k) * 128 + c * 4];
        }
        __syncthreads();
#pragma unroll
        for (int k = 0; k < 16; k++) {
            float a[8], bb[8];
            *(float4*)&a[0]  = *(float4*)&As[k][ty * 8];
            *(float4*)&a[4]  = *(float4*)&As[k][ty * 8 + 4];
            *(float4*)&bb[0] = *(float4*)&Bs[k][tx * 8];
            *(float4*)&bb[4] = *(float4*)&Bs[k][tx * 8 + 4];
#pragma unroll
            for (int i = 0; i < 8; i++)
#pragma unroll
                for (int j = 0; j < 8; j++)
                    acc[i][j] += a[i] * bb[j];
        }
        __syncthreads();
    }
#pragma unroll
    for (int i = 0; i < 8; i++) {
        int gr = row0 + ty * 8 + i;
        if (gr >= N_NODES) continue;
        *(float4*)&C[(size_t)gr * 128 + tx * 8] =
            make_float4(acc[i][0], acc[i][1], acc[i][2], acc[i][3]);
        *(float4*)&C[(size_t)gr * 128 + tx * 8 + 4] =
            make_float4(acc[i][4], acc[i][5], acc[i][6], acc[i][7]);
    }
}

// ---------------- final: sigmoid(h[N,128] @ Wfc[128,1] + bfc) ----------------
__global__ void out_kernel(const float* __restrict__ h,
                           const float* __restrict__ Wfc,
                           const float* __restrict__ bfc,
                           float* __restrict__ out) {
    int gid = blockIdx.x * blockDim.x + threadIdx.x;
    int n = gid >> 5, lane = gid & 31;
    if (n >= N_NODES) return;
    const float* hp = h + (size_t)n * 128;
    float s = hp[lane]      * Wfc[lane]
            + hp[lane + 32] * Wfc[lane + 32]
            + hp[lane + 64] * Wfc[lane + 64]
            + hp[lane + 96] * Wfc[lane + 96];
#pragma unroll
    for (int o = 16; o > 0; o >>= 1) s += __shfl_down_sync(0xffffffffu, s, o);
    if (lane == 0) {
        float v = s + bfc[0];
        out[n] = 1.f / (1.f + __expf(-v));
    }
}

// ---------------- launch ----------------
extern "C" void kernel_launch(void* const* d_in, const int* in_sizes, int n_in,
                              void* d_out, int out_size) {
    const float* x      = (const float*)d_in[0];
    const int*   ei     = (const int*)  d_in[1];
    const float* W1     = (const float*)d_in[2];
    const float* a_src1 = (const float*)d_in[3];
    const float* a_dst1 = (const float*)d_in[4];
    const float* b1     = (const float*)d_in[5];
    const float* W2     = (const float*)d_in[6];
    const float* a_src2 = (const float*)d_in[7];
    const float* a_dst2 = (const float*)d_in[8];
    const float* b2     = (const float*)d_in[9];
    const float* Wfc    = (const float*)d_in[10];
    const float* bfc    = (const float*)d_in[11];
    float* out = (float*)d_out;

    int E  = in_sizes[1] / 2;
    int ET = E + N_NODES;

    float *h1, *agg1, *h2, *agg2, *ss, *sd, *m, *z;
    cudaGetSymbolAddress((void**)&h1,   g_h1);
    cudaGetSymbolAddress((void**)&agg1, g_agg1);
    cudaGetSymbolAddress((void**)&h2,   g_h2);
    cudaGetSymbolAddress((void**)&agg2, g_agg2);
    cudaGetSymbolAddress((void**)&ss,   g_ss);
    cudaGetSymbolAddress((void**)&sd,   g_sd);
    cudaGetSymbolAddress((void**)&m,    g_m);
    cudaGetSymbolAddress((void**)&z,    g_z);

    const int TB = 256;

    // ===== layer 1 (H=4, F=256) =====
    gemm1_kernel<<<(N_NODES + 63) / 64, TB>>>(x, W1, h1);
    scores_kernel<H1><<<(N_NODES * H1 * 32 + TB - 1) / TB, TB>>>(h1, a_src1, a_dst1, ss, sd);
    cudaMemsetAsync(agg1, 0, (size_t)N_NODES * F1 * sizeof(float));
    init_mz_kernel<H1><<<(N_NODES * H1 + TB - 1) / TB, TB>>>(m, z);
    edge_max_kernel<H1><<<(ET + TB - 1) / TB, TB>>>(ei, E, ET, ss, sd, m);
    edge_agg_kernel<H1, F1><<<(ET * 32 + TB - 1) / TB, TB>>>(ei, E, ET, ss, sd, m, z, h1, agg1);
    finalize_kernel<H1, F1><<<(N_NODES * F1 + TB - 1) / TB, TB>>>(agg1, z, b1);

    // ===== layer 2 (H=2, F=128) =====
    gemm2_kernel<<<(N_NODES + 127) / 128, TB>>>(agg1, W2, h2);
    scores_kernel<H2><<<(N_NODES * H2 * 32 + TB - 1) / TB, TB>>>(h2, a_src2, a_dst2, ss, sd);
    cudaMemsetAsync(agg2, 0, (size_t)N_NODES * F2 * sizeof(float));
    init_mz_kernel<H2><<<(N_NODES * H2 + TB - 1) / TB, TB>>>(m, z);
    edge_max_kernel<H2><<<(ET + TB - 1) / TB, TB>>>(ei, E, ET, ss, sd, m);
    edge_agg_kernel<H2, F2><<<(ET * 32 + TB - 1) / TB, TB>>>(ei, E, ET, ss, sd, m, z, h2, agg2);
    finalize_kernel<H2, F2><<<(N_NODES * F2 + TB - 1) / TB, TB>>>(agg2, z, b2);

    // ===== final linear + sigmoid =====
    out_kernel<<<(N_NODES * 32 + TB - 1) / TB, TB>>>(agg2, Wfc, bfc, out);
}